// round 10
// baseline (speedup 1.0000x reference)
#include <cuda_runtime.h>
#include <cuda_bf16.h>

// Shapes (fixed): B=16, TE=TD=128, H=256
#define Bsz 16
#define TT 128
#define HH 256
#define MROWS (Bsz*TT)   // 2048
#define NCTA 128

typedef unsigned long long u64;

// Scratch (device globals; no allocation allowed)
__device__ float g_enc[MROWS*HH];    // orthogonalized encoder [B*TE][H]
__device__ float g_wasT[MROWS*HH];   // (enc_ortho @ W_a) TRANSPOSED: [b][h][e]
__device__ float g_uah[MROWS*HH];    // dec @ U_a  (row-major)

// grid barrier state (generation is monotonic across launches -> deterministic)
__device__ unsigned g_barcnt = 0;
__device__ volatile unsigned g_bargen = 0;

__device__ __forceinline__ void grid_barrier() {
    // EVERY thread fences its global writes before arrival: BAR.SYNC drains
    // STS but NOT STG; thread-0's fence alone does not cover peers' stores.
    __threadfence();
    __syncthreads();
    if (threadIdx.x == 0) {
        unsigned gen = g_bargen;
        if (atomicAdd(&g_barcnt, 1) == NCTA - 1) {
            g_barcnt = 0;
            __threadfence();          // release: reset + prior state before gen bump
            g_bargen = gen + 1;
        } else {
            while (g_bargen == gen) { }
        }
        __threadfence();              // acquire
    }
    __syncthreads();
}

__device__ __forceinline__ float tanh_fast(float x) {
    float y;
    asm("tanh.approx.f32 %0, %1;" : "=f"(y) : "f"(x));
    return y;
}
__device__ __forceinline__ u64 pack2(float lo, float hi) {
    u64 r; asm("mov.b64 %0, {%1, %2};" : "=l"(r) : "f"(lo), "f"(hi)); return r;
}
__device__ __forceinline__ void unpack2(u64 v, float& a, float& b) {
    asm("mov.b64 {%0, %1}, %2;" : "=f"(a), "=f"(b) : "l"(v));
}
__device__ __forceinline__ void fma2(u64& d, u64 a, u64 b) {
    asm("fma.rn.f32x2 %0, %1, %2, %0;" : "+l"(d) : "l"(a), "l"(b));
}

#define WTP 132
#define VBM 132   // As row pad (phase B)
#define VBN 36    // Bs row pad (phase B)
#define VSZ (32*VBM + 32*VBN)   // floats per virtual CTA

// ---------------------------------------------------------------------------
// One persistent kernel: 128 CTAs x 512 threads, 3 phases with grid barriers.
// ---------------------------------------------------------------------------
__global__ __launch_bounds__(512) void fused_kernel(const float* __restrict__ enc,
                                                    const float* __restrict__ dec,
                                                    const float* __restrict__ Wa,
                                                    const float* __restrict__ Ua,
                                                    const float* __restrict__ Va,
                                                    float* __restrict__ eo,
                                                    float* __restrict__ co) {
    extern __shared__ float smem[];
    int cid = blockIdx.x;
    int tid = threadIdx.x;

    // ================= Phase A: orthogonalize =================
    // out[t] = x[t] - sum_{j<t} x[j]  (identity of x - ((x*s)/(x*x))*x)
    {
        int b  = cid & 15;
        int hb = cid >> 4;               // 0..7 (32 h each)
        int seg = tid >> 3;              // 0..63 (2 timesteps each)
        int hq  = tid & 7;
        int h = hb * 32 + hq * 4;
        int t0 = seg * 2;

        const float4* base = (const float4*)(enc + (size_t)(b * TT + t0) * HH + h);
        float4* obase = (float4*)(g_enc + (size_t)(b * TT + t0) * HH + h);
        float4 x0 = base[0];
        float4 x1 = base[HH / 4];

        float4* part = (float4*)smem;    // [64][8]
        float4 ps = {x0.x + x1.x, x0.y + x1.y, x0.z + x1.z, x0.w + x1.w};
        part[seg * 8 + hq] = ps;
        __syncthreads();

        float4 run = {0.f, 0.f, 0.f, 0.f};
        for (int s = 0; s < seg; s++) {
            float4 p = part[s * 8 + hq];
            run.x += p.x; run.y += p.y; run.z += p.z; run.w += p.w;
        }
        float4 o0 = {x0.x - run.x, x0.y - run.y, x0.z - run.z, x0.w - run.w};
        obase[0] = o0;
        run.x += x0.x; run.y += x0.y; run.z += x0.z; run.w += x0.w;
        float4 o1 = {x1.x - run.x, x1.y - run.y, x1.z - run.z, x1.w - run.w};
        obase[HH / 4] = o1;
    }
    grid_barrier();

    // ================= Phase B: two GEMMs as 256 virtual CTAs =================
    // vid < 128: g_enc @ W_a -> g_wasT (transposed [b][h][e]); tile (mb=b, nb)
    // vid >=128: dec @ U_a -> g_uah (row-major)
    // BM=128, BN=32, BK=32; 256 threads per vCTA (named barriers 1/2).
    {
        int vh = tid >> 8;               // which virtual CTA in this block
        int w  = tid & 255;
        int vid = cid * 2 + vh;          // 0..255
        bool isWas = vid < 128;
        int v = isWas ? vid : vid - 128;
        int mb = v >> 3, nb = v & 7;
        const float* A = isWas ? g_enc : dec;
        const float* W = isWas ? Wa : Ua;
        int mblk = mb * 128, nblk = nb * 32;
        float* As = smem + vh * VSZ;
        float* Bs = As + 32 * VBM;
        int barid = 1 + vh;

        int tr = w >> 3, tc = w & 7;
        int m0 = tr * 4, n0 = tc * 4;
        u64 acc2[2][4] = {};             // 2 m-pairs x 4 n

        float4 pa[4], pb;
        #define LOADT(kt) { \
            _Pragma("unroll") \
            for (int q = 0; q < 4; q++) { int s = w + q * 256; int m = s >> 3, kq = s & 7; \
                pa[q] = *(const float4*)&A[(size_t)(mblk + m) * HH + (kt) * 32 + kq * 4]; } \
            { int k = w >> 3, nq = w & 7; \
                pb = *(const float4*)&W[(size_t)((kt) * 32 + k) * HH + nblk + nq * 4]; } }

        LOADT(0);
        for (int kt = 0; kt < 8; kt++) {
            asm volatile("bar.sync %0, 256;" :: "r"(barid) : "memory");
            #pragma unroll
            for (int q = 0; q < 4; q++) {
                int s = w + q * 256; int m = s >> 3, kq = s & 7;
                As[(kq * 4 + 0) * VBM + m] = pa[q].x;
                As[(kq * 4 + 1) * VBM + m] = pa[q].y;
                As[(kq * 4 + 2) * VBM + m] = pa[q].z;
                As[(kq * 4 + 3) * VBM + m] = pa[q].w;
            }
            {
                int k = w >> 3, nq = w & 7;
                *(float4*)&Bs[k * VBN + nq * 4] = pb;
            }
            asm volatile("bar.sync %0, 256;" :: "r"(barid) : "memory");
            if (kt < 7) LOADT(kt + 1);

            #pragma unroll
            for (int kk = 0; kk < 32; kk++) {
                ulonglong2 aA = *(const ulonglong2*)&As[kk * VBM + m0];
                float4 bb = *(const float4*)&Bs[kk * VBN + n0];
                u64 b0 = pack2(bb.x, bb.x);
                u64 b1 = pack2(bb.y, bb.y);
                u64 b2 = pack2(bb.z, bb.z);
                u64 b3 = pack2(bb.w, bb.w);
                fma2(acc2[0][0], aA.x, b0); fma2(acc2[0][1], aA.x, b1);
                fma2(acc2[0][2], aA.x, b2); fma2(acc2[0][3], aA.x, b3);
                fma2(acc2[1][0], aA.y, b0); fma2(acc2[1][1], aA.y, b1);
                fma2(acc2[1][2], aA.y, b2); fma2(acc2[1][3], aA.y, b3);
            }
        }
        #undef LOADT

        if (isWas) {
            // transposed: g_wasT[b][h][e]; e = m0..m0+3 contiguous per h column
            float* baseT = g_wasT + (size_t)mb * (HH * TT);
            #pragma unroll
            for (int j = 0; j < 4; j++) {
                float v0, v1, v2, v3;
                unpack2(acc2[0][j], v0, v1);
                unpack2(acc2[1][j], v2, v3);
                float4 q = {v0, v1, v2, v3};
                *(float4*)&baseT[(size_t)(nblk + n0 + j) * TT + m0] = q;
            }
        } else {
            #pragma unroll
            for (int i = 0; i < 2; i++) {
                float lo[4], hi[4];
                #pragma unroll
                for (int j = 0; j < 4; j++) unpack2(acc2[i][j], lo[j], hi[j]);
                float4 o0 = {lo[0], lo[1], lo[2], lo[3]};
                float4 o1 = {hi[0], hi[1], hi[2], hi[3]};
                *(float4*)&g_uah[(size_t)(mblk + m0 + 2 * i) * HH + nblk + n0] = o0;
                *(float4*)&g_uah[(size_t)(mblk + m0 + 2 * i + 1) * HH + nblk + n0] = o1;
            }
        }
    }
    grid_barrier();

    // ================= Phase C: energy + softmax + context =================
    {
        float* was_t = smem;                  // 256*132
        float* uah_t = was_t + 256 * WTP;     // 256*20
        float* Vs    = uah_t + 256 * 20;      // 256
        float* Es = smem;                     // phase-2 overlay: [128 e][256 h]
        float* Pt = smem + 32768;             // [16 d][128 e]

        int db = cid >> 4;
        int b  = cid & 15;

        const float* wsrc = g_wasT + (size_t)b * (HH * TT);
        for (int idx = tid; idx < HH * TT; idx += 512) {
            int h = idx >> 7, e = idx & 127;
            was_t[h * WTP + e] = wsrc[idx];
        }
        for (int idx = tid; idx < 16 * HH; idx += 512) {
            int dd = idx >> 8, h = idx & 255;
            uah_t[h * 20 + dd] = g_uah[(size_t)(b * TT + db * 16 + dd) * HH + h];
        }
        if (tid < 256) Vs[tid] = Va[tid];
        __syncthreads();

        int eg = tid & 31, dg = tid >> 5;    // dg = warp = d-row (0..15)
        int e0 = eg * 4;
        const float* wp = was_t + e0;
        const float* up = uah_t + dg;

        float a0 = 0.f, a1 = 0.f, a2 = 0.f, a3 = 0.f;
        #pragma unroll 4
        for (int h = 0; h < HH; h++) {
            float4 w4 = *(const float4*)(wp + h * WTP);
            float u = up[h * 20];
            float v = Vs[h];
            a0 += v * tanh_fast(u + w4.x);
            a1 += v * tanh_fast(u + w4.y);
            a2 += v * tanh_fast(u + w4.z);
            a3 += v * tanh_fast(u + w4.w);
        }

        float m = fmaxf(fmaxf(a0, a1), fmaxf(a2, a3));
        #pragma unroll
        for (int o = 16; o > 0; o >>= 1) m = fmaxf(m, __shfl_xor_sync(0xffffffffu, m, o));
        float x0 = __expf(a0 - m), x1 = __expf(a1 - m);
        float x2 = __expf(a2 - m), x3 = __expf(a3 - m);
        float ssum = x0 + x1 + x2 + x3;
        #pragma unroll
        for (int o = 16; o > 0; o >>= 1) ssum += __shfl_xor_sync(0xffffffffu, ssum, o);
        float inv = 1.f / ssum;
        float4 p4 = {x0 * inv, x1 * inv, x2 * inv, x3 * inv};
        *(float4*)&eo[(size_t)(b * TT + db * 16 + dg) * TT + e0] = p4;

        __syncthreads();   // all reads of was_t/uah_t done before overlay

        *(float4*)&Pt[dg * 128 + e0] = p4;
        #pragma unroll
        for (int t = tid; t < (TT * HH) / 4; t += 512) {
            int e = t >> 6, hq = t & 63;
            *(float4*)&Es[e * HH + hq * 4] =
                *(const float4*)&g_enc[(size_t)(b * TT + e) * HH + hq * 4];
        }
        __syncthreads();

        int mp = tid >> 6, tc2 = tid & 63;
        int m0 = mp * 2, n0 = tc2 * 4;
        const float* p0r = Pt + m0 * 128;
        const float* p1r = Pt + (m0 + 1) * 128;
        const float* er  = Es + n0;

        u64 acc2[2][2] = {};
        #pragma unroll 4
        for (int k = 0; k < 128; k++) {
            float pv0 = p0r[k];
            float pv1 = p1r[k];
            ulonglong2 ev = *(const ulonglong2*)(er + k * HH);
            u64 pa0 = pack2(pv0, pv0);
            u64 pa1 = pack2(pv1, pv1);
            fma2(acc2[0][0], pa0, ev.x); fma2(acc2[0][1], pa0, ev.y);
            fma2(acc2[1][0], pa1, ev.x); fma2(acc2[1][1], pa1, ev.y);
        }

        #pragma unroll
        for (int i = 0; i < 2; i++) {
            float l0, h0, l1, h1;
            unpack2(acc2[i][0], l0, h0);
            unpack2(acc2[i][1], l1, h1);
            float4 r = {l0, h0, l1, h1};
            *(float4*)&co[(size_t)(b * TT + db * 16 + m0 + i) * HH + n0] = r;
        }
    }
}

// ---------------------------------------------------------------------------
extern "C" void kernel_launch(void* const* d_in, const int* in_sizes, int n_in,
                              void* d_out, int out_size) {
    const float* enc = (const float*)d_in[0];
    const float* dec = (const float*)d_in[1];
    const float* Wa  = (const float*)d_in[2];
    const float* Ua  = (const float*)d_in[3];
    const float* Va  = (const float*)d_in[4];

    float* co = (float*)d_out;                    // c_outputs [16,128,256]
    float* eo = co + Bsz * TT * HH;               // e_outputs [16,128,128]

    const int SMX = (256 * WTP + 256 * 20 + 256) * 4;   // 156672 B (phase C max)
    static bool attr_done = false;
    if (!attr_done) {
        cudaFuncSetAttribute(fused_kernel,
                             cudaFuncAttributeMaxDynamicSharedMemorySize, SMX);
        attr_done = true;
    }

    fused_kernel<<<NCTA, 512, SMX>>>(enc, dec, Wa, Ua, Va, eo, co);
}

// round 11
// speedup vs baseline: 1.0176x; 1.0176x over previous
#include <cuda_runtime.h>
#include <cuda_bf16.h>

// Shapes (fixed): B=16, TE=TD=128, H=256
#define Bsz 16
#define TT 128
#define HH 256
#define MROWS (Bsz*TT)   // 2048

typedef unsigned long long u64;

// Scratch (device globals; no allocation allowed)
__device__ float g_enc[MROWS*HH];    // orthogonalized encoder [B*TE][H]
__device__ float g_wasT[MROWS*HH];   // (enc_ortho @ W_a) TRANSPOSED: [b][h][e]
__device__ float g_uah[MROWS*HH];    // dec @ U_a  (row-major)

__device__ __forceinline__ float tanh_fast(float x) {
    float y;
    asm("tanh.approx.f32 %0, %1;" : "=f"(y) : "f"(x));
    return y;
}
__device__ __forceinline__ u64 pack2(float lo, float hi) {
    u64 r; asm("mov.b64 %0, {%1, %2};" : "=l"(r) : "f"(lo), "f"(hi)); return r;
}
__device__ __forceinline__ void unpack2(u64 v, float& a, float& b) {
    asm("mov.b64 {%0, %1}, %2;" : "=f"(a), "=f"(b) : "l"(v));
}
__device__ __forceinline__ void fma2(u64& d, u64 a, u64 b) {
    asm("fma.rn.f32x2 %0, %1, %2, %0;" : "+l"(d) : "l"(a), "l"(b));
}
__device__ __forceinline__ void add2(u64& d, u64 a) {
    asm("add.rn.f32x2 %0, %0, %1;" : "+l"(d) : "l"(a));
}

// ---------------------------------------------------------------------------
// K1: orthogonalize. out[t] = x[t] - sum_{j<t} x[j]  (elementwise identity of
// x - ((x*s)/(x*x))*x). grid (8 hb, 16 b), 512 threads = 64 segs x 8 lanes.
// ---------------------------------------------------------------------------
__global__ __launch_bounds__(512) void ortho_kernel(const float* __restrict__ enc) {
    int hb = blockIdx.x;             // 0..7 (32 h each)
    int b  = blockIdx.y;
    int tid = threadIdx.x;
    int seg = tid >> 3;              // 0..63 (2 timesteps each)
    int hq  = tid & 7;
    int h = hb * 32 + hq * 4;
    int t0 = seg * 2;

    const float4* base = (const float4*)(enc + (size_t)(b * TT + t0) * HH + h);
    float4* obase = (float4*)(g_enc + (size_t)(b * TT + t0) * HH + h);
    float4 x0 = base[0];
    float4 x1 = base[HH / 4];

    __shared__ float4 part[64][8];
    float4 ps = {x0.x + x1.x, x0.y + x1.y, x0.z + x1.z, x0.w + x1.w};
    part[seg][hq] = ps;
    __syncthreads();

    float4 run = {0.f, 0.f, 0.f, 0.f};
    for (int s = 0; s < seg; s++) {
        float4 p = part[s][hq];
        run.x += p.x; run.y += p.y; run.z += p.z; run.w += p.w;
    }
    float4 o0 = {x0.x - run.x, x0.y - run.y, x0.z - run.z, x0.w - run.w};
    obase[0] = o0;
    run.x += x0.x; run.y += x0.y; run.z += x0.z; run.w += x0.w;
    float4 o1 = {x1.x - run.x, x1.y - run.y, x1.z - run.z, x1.w - run.w};
    obase[HH / 4] = o1;
}

// ---------------------------------------------------------------------------
// K2: two GEMMs [2048,256]@[256,256]. BM=64 BN=128 BK=32, 128 threads,
// 8m x 8n microtile (1 B LDS per FMA -> FFMA2-floor bound).
// grid (32 mb, 2 nb, 2 z) = 128 CTAs.
// z=0: g_enc @ W_a -> g_wasT ([b][h][e]); z=1: dec @ U_a -> g_uah.
// ---------------------------------------------------------------------------
#define GBM 68    // As pad  ([k][m], m=64)
#define GBN 132   // Bs pad  ([k][n], n=128)
__global__ __launch_bounds__(128) void gemm2_kernel(const float* __restrict__ dec,
                                                    const float* __restrict__ Wa,
                                                    const float* __restrict__ Ua) {
    const float *A, *W;
    if (blockIdx.z == 0) { A = g_enc; W = Wa; }
    else                 { A = dec;   W = Ua; }

    __shared__ __align__(16) float As[32 * GBM];
    __shared__ __align__(16) float Bs[32 * GBN];

    int tid = threadIdx.x;
    int mblk = blockIdx.x * 64;
    int nblk = blockIdx.y * 128;

    float4 pa[4], pb[8];
    #define LOADT(kt) { \
        _Pragma("unroll") \
        for (int q = 0; q < 4; q++) { int s = tid + q * 128; int m = s >> 3, kq = s & 7; \
            pa[q] = *(const float4*)&A[(size_t)(mblk + m) * HH + (kt) * 32 + kq * 4]; } \
        _Pragma("unroll") \
        for (int q = 0; q < 8; q++) { int s = tid + q * 128; int k = s >> 5, nq = s & 31; \
            pb[q] = *(const float4*)&W[(size_t)((kt) * 32 + k) * HH + nblk + nq * 4]; } }

    int tr = tid >> 4, tc = tid & 15;
    int m0 = tr * 8, n0 = tc * 8;
    u64 acc[4][8] = {};   // 4 m-pairs x 8 n

    LOADT(0);
    for (int kt = 0; kt < 8; kt++) {
        __syncthreads();
        #pragma unroll
        for (int q = 0; q < 4; q++) {
            int s = tid + q * 128; int m = s >> 3, kq = s & 7;
            As[(kq * 4 + 0) * GBM + m] = pa[q].x;
            As[(kq * 4 + 1) * GBM + m] = pa[q].y;
            As[(kq * 4 + 2) * GBM + m] = pa[q].z;
            As[(kq * 4 + 3) * GBM + m] = pa[q].w;
        }
        #pragma unroll
        for (int q = 0; q < 8; q++) {
            int s = tid + q * 128; int k = s >> 5, nq = s & 31;
            *(float4*)&Bs[k * GBN + nq * 4] = pb[q];
        }
        __syncthreads();
        if (kt < 7) LOADT(kt + 1);

        #pragma unroll
        for (int kk = 0; kk < 32; kk++) {
            ulonglong2 aA = *(const ulonglong2*)&As[kk * GBM + m0];
            ulonglong2 aB = *(const ulonglong2*)&As[kk * GBM + m0 + 4];
            float4 b0 = *(const float4*)&Bs[kk * GBN + n0];
            float4 b1 = *(const float4*)&Bs[kk * GBN + n0 + 4];
            u64 am[4] = {aA.x, aA.y, aB.x, aB.y};
            u64 bn[8] = {pack2(b0.x, b0.x), pack2(b0.y, b0.y),
                         pack2(b0.z, b0.z), pack2(b0.w, b0.w),
                         pack2(b1.x, b1.x), pack2(b1.y, b1.y),
                         pack2(b1.z, b1.z), pack2(b1.w, b1.w)};
            #pragma unroll
            for (int i = 0; i < 4; i++)
                #pragma unroll
                for (int j = 0; j < 8; j++)
                    fma2(acc[i][j], am[i], bn[j]);
        }
    }
    #undef LOADT

    if (blockIdx.z == 0) {
        // transposed: g_wasT[b][h][e]; e = (mblk&127)+m0.. contiguous, 8 h cols
        int bb = mblk >> 7;
        int e0 = (mblk & 127) + m0;
        float* baseT = g_wasT + (size_t)bb * (HH * TT);
        #pragma unroll
        for (int j = 0; j < 8; j++) {
            float v[8];
            #pragma unroll
            for (int i = 0; i < 4; i++) unpack2(acc[i][j], v[2 * i], v[2 * i + 1]);
            float4 q0 = {v[0], v[1], v[2], v[3]};
            float4 q1 = {v[4], v[5], v[6], v[7]};
            float* col = baseT + (size_t)(nblk + n0 + j) * TT + e0;
            *(float4*)col = q0;
            *(float4*)(col + 4) = q1;
        }
    } else {
        #pragma unroll
        for (int i = 0; i < 4; i++) {
            float lo[8], hi[8];
            #pragma unroll
            for (int j = 0; j < 8; j++) unpack2(acc[i][j], lo[j], hi[j]);
            float4 a0 = {lo[0], lo[1], lo[2], lo[3]};
            float4 a1 = {lo[4], lo[5], lo[6], lo[7]};
            float4 c0 = {hi[0], hi[1], hi[2], hi[3]};
            float4 c1 = {hi[4], hi[5], hi[6], hi[7]};
            float* r0 = &g_uah[(size_t)(mblk + m0 + 2 * i) * HH + nblk + n0];
            float* r1 = &g_uah[(size_t)(mblk + m0 + 2 * i + 1) * HH + nblk + n0];
            *(float4*)r0 = a0; *(float4*)(r0 + 4) = a1;
            *(float4*)r1 = c0; *(float4*)(r1 + 4) = c1;
        }
    }
}

// ---------------------------------------------------------------------------
// K3 (fused): energy + softmax + context. grid (8 dblocks, 16 b), block 512.
// Context: 4m x 4n microtile, 2-way k-split across thread halves, packed
// f32x2 reduction through SMEM.
// ---------------------------------------------------------------------------
#define WTP 132
#define RSTR 18   // reduction scratch row stride (floats; even, conflict-light)
__global__ __launch_bounds__(512) void energy_ctx_kernel(const float* __restrict__ Va,
                                                         float* __restrict__ eo,
                                                         float* __restrict__ co) {
    extern __shared__ float sm3[];
    float* was_t = sm3;                  // 256*132
    float* uah_t = was_t + 256 * WTP;    // 256*20
    float* Vs    = uah_t + 256 * 20;     // 256
    float* Es = sm3;                     // overlay: [128 e][256 h]
    float* Pt = sm3 + 32768;             // [16 d][128 e]
    float* red = sm3;                    // reduction scratch (reuses Es after k-loop)

    int db = blockIdx.x;
    int b  = blockIdx.y;
    int tid = threadIdx.x;

    const float* wsrc = g_wasT + (size_t)b * (HH * TT);
    for (int idx = tid; idx < HH * TT; idx += 512) {
        int h = idx >> 7, e = idx & 127;
        was_t[h * WTP + e] = wsrc[idx];
    }
    for (int idx = tid; idx < 16 * HH; idx += 512) {
        int dd = idx >> 8, h = idx & 255;
        uah_t[h * 20 + dd] = g_uah[(size_t)(b * TT + db * 16 + dd) * HH + h];
    }
    if (tid < 256) Vs[tid] = Va[tid];
    __syncthreads();

    int eg = tid & 31, dg = tid >> 5;    // dg = warp = d-row (0..15)
    int e0 = eg * 4;
    const float* wp = was_t + e0;
    const float* up = uah_t + dg;

    float a0 = 0.f, a1 = 0.f, a2 = 0.f, a3 = 0.f;
    #pragma unroll 4
    for (int h = 0; h < HH; h++) {
        float4 w4 = *(const float4*)(wp + h * WTP);
        float u = up[h * 20];
        float v = Vs[h];
        a0 += v * tanh_fast(u + w4.x);
        a1 += v * tanh_fast(u + w4.y);
        a2 += v * tanh_fast(u + w4.z);
        a3 += v * tanh_fast(u + w4.w);
    }

    float m = fmaxf(fmaxf(a0, a1), fmaxf(a2, a3));
    #pragma unroll
    for (int o = 16; o > 0; o >>= 1) m = fmaxf(m, __shfl_xor_sync(0xffffffffu, m, o));
    float x0 = __expf(a0 - m), x1 = __expf(a1 - m);
    float x2 = __expf(a2 - m), x3 = __expf(a3 - m);
    float ssum = x0 + x1 + x2 + x3;
    #pragma unroll
    for (int o = 16; o > 0; o >>= 1) ssum += __shfl_xor_sync(0xffffffffu, ssum, o);
    float inv = 1.f / ssum;
    float4 p4 = {x0 * inv, x1 * inv, x2 * inv, x3 * inv};
    *(float4*)&eo[(size_t)(b * TT + db * 16 + dg) * TT + e0] = p4;

    // ---- context ----
    __syncthreads();   // reads of was_t/uah_t done before overlay

    *(float4*)&Pt[dg * 128 + e0] = p4;
    #pragma unroll
    for (int t = tid; t < (TT * HH) / 4; t += 512) {
        int e = t >> 6, hq = t & 63;
        *(float4*)&Es[e * HH + hq * 4] =
            *(const float4*)&g_enc[(size_t)(b * TT + e) * HH + hq * 4];
    }
    __syncthreads();

    // C[16,256] = P[16,128] @ E[128,256]; 2-way k-split, 4m x 4n per thread.
    int kg = tid >> 8;                // 0,1 -> k-half
    int t2 = tid & 255;
    int tr = t2 >> 6;                 // 0..3
    int tc = t2 & 63;                 // 0..63
    int m0 = tr * 4, n0 = tc * 4;
    int kbase = kg * 64;

    u64 acc[4][2] = {};   // [m][n-pair]
    #pragma unroll 4
    for (int kk = 0; kk < 64; kk++) {
        int k = kbase + kk;
        ulonglong2 ev = *(const ulonglong2*)&Es[k * HH + n0];
        float p0 = Pt[(m0 + 0) * 128 + k];
        float p1 = Pt[(m0 + 1) * 128 + k];
        float p2 = Pt[(m0 + 2) * 128 + k];
        float p3 = Pt[(m0 + 3) * 128 + k];
        u64 q0 = pack2(p0, p0), q1 = pack2(p1, p1);
        u64 q2 = pack2(p2, p2), q3 = pack2(p3, p3);
        fma2(acc[0][0], q0, ev.x); fma2(acc[0][1], q0, ev.y);
        fma2(acc[1][0], q1, ev.x); fma2(acc[1][1], q1, ev.y);
        fma2(acc[2][0], q2, ev.x); fma2(acc[2][1], q2, ev.y);
        fma2(acc[3][0], q3, ev.x); fma2(acc[3][1], q3, ev.y);
    }
    __syncthreads();   // Es reads done; red may overwrite

    if (kg == 1) {
        #pragma unroll
        for (int i = 0; i < 4; i++) {
            *(u64*)&red[t2 * RSTR + 4 * i + 0] = acc[i][0];
            *(u64*)&red[t2 * RSTR + 4 * i + 2] = acc[i][1];
        }
    }
    __syncthreads();
    if (kg == 0) {
        #pragma unroll
        for (int i = 0; i < 4; i++) {
            add2(acc[i][0], *(const u64*)&red[t2 * RSTR + 4 * i + 0]);
            add2(acc[i][1], *(const u64*)&red[t2 * RSTR + 4 * i + 2]);
            float l0, h0, l1, h1;
            unpack2(acc[i][0], l0, h0);
            unpack2(acc[i][1], l1, h1);
            float4 r = {l0, h0, l1, h1};
            *(float4*)&co[(size_t)(b * TT + db * 16 + m0 + i) * HH + n0] = r;
        }
    }
}

// ---------------------------------------------------------------------------
extern "C" void kernel_launch(void* const* d_in, const int* in_sizes, int n_in,
                              void* d_out, int out_size) {
    const float* enc = (const float*)d_in[0];
    const float* dec = (const float*)d_in[1];
    const float* Wa  = (const float*)d_in[2];
    const float* Ua  = (const float*)d_in[3];
    const float* Va  = (const float*)d_in[4];

    float* co = (float*)d_out;                    // c_outputs [16,128,256]
    float* eo = co + Bsz * TT * HH;               // e_outputs [16,128,128]

    const int SM3 = (256 * WTP + 256 * 20 + 256) * 4;   // 156672 B
    static bool attr_done = false;
    if (!attr_done) {
        cudaFuncSetAttribute(energy_ctx_kernel,
                             cudaFuncAttributeMaxDynamicSharedMemorySize, SM3);
        attr_done = true;
    }

    ortho_kernel<<<dim3(8, 16), 512>>>(enc);
    gemm2_kernel<<<dim3(32, 2, 2), 128>>>(dec, Wa, Ua);
    energy_ctx_kernel<<<dim3(8, 16), 512, SM3>>>(Va, eo, co);
}